// round 8
// baseline (speedup 1.0000x reference)
#include <cuda_runtime.h>

#define EMB 64
#define NL_MAX 50000
#define NR_MAX 100000
#define NE_MAX 1000000
#define BN_EPS 1e-5f

#define WPAD 68         // wsT row pad (16B-aligned rows)
#define TROWS 96        // rows per block tile
#define RPTN 6          // rows per thread (16 row-groups x 6)

typedef unsigned long long u64;

__device__ __forceinline__ u64 pack2(float lo, float hi) {
    u64 r; asm("mov.b64 %0, {%1,%2};" : "=l"(r) : "f"(lo), "f"(hi)); return r;
}
__device__ __forceinline__ void fma2(u64& acc, u64 a, u64 b) {
    asm("fma.rn.f32x2 %0, %1, %2, %0;" : "+l"(acc) : "l"(a), "l"(b));
}
__device__ __forceinline__ float2 unpack2(u64 v) {
    float2 f; asm("mov.b64 {%0,%1}, %2;" : "=f"(f.x), "=f"(f.y) : "l"(v)); return f;
}

// ---------------- scratch ----------------------------------------------------
__device__ float d_LP[NL_MAX * EMB];
__device__ float d_RP[NR_MAX * EMB];
__device__ float d_S[NR_MAX * EMB];
__device__ float d_conv[NR_MAX * EMB];
__device__ float d_deg[NR_MAX];
__device__ float d_stats[256];   // [0:64) sum1, [64:128) sq1, [128:192) sum2, [192:256) sq2

// ---------------- GEMM body: direct-LDG x (L1 broadcast), wsT staged ---------
// MODE 0: out = X@W.T ; 1: +bias ; 2: +deg*bias & bn2 stats into d_stats[128..]
template <int MODE>
__device__ __forceinline__ void gemm_body(
    const float* __restrict__ X, const float* __restrict__ W,
    const float* __restrict__ bias, const float* __restrict__ deg,
    float* __restrict__ out, int nrows, int blk,
    float (*wsT)[WPAD], float* red)
{
    int t = threadIdx.x;
    int cg = t & 15;
    int rg = t >> 4;
    int row0 = blk * TROWS;
    int ca = 4 * cg;
    int r0 = rg * RPTN;

    // stage W transposed, coalesced
#pragma unroll
    for (int p = 0; p < 4; p++) {
        int i = t + p * 256;
        int c = i >> 4;
        int k4 = (i & 15) * 4;
        float4 w4 = *(const float4*)&W[c * EMB + k4];
        wsT[k4 + 0][c] = w4.x;
        wsT[k4 + 1][c] = w4.y;
        wsT[k4 + 2][c] = w4.z;
        wsT[k4 + 3][c] = w4.w;
    }
    __syncthreads();

    // clamped row indices (avoid divergence; garbage rows masked at store)
    int grj[RPTN];
#pragma unroll
    for (int j = 0; j < RPTN; j++) {
        int gr = row0 + r0 + j;
        grj[j] = gr < nrows ? gr : (nrows - 1);
    }

    u64 acc0[RPTN], acc1[RPTN];
    if (MODE == 0) {
#pragma unroll
        for (int j = 0; j < RPTN; j++) { acc0[j] = pack2(0.f, 0.f); acc1[j] = pack2(0.f, 0.f); }
    } else if (MODE == 1) {
        u64 b01 = pack2(bias[ca], bias[ca + 1]);
        u64 b23 = pack2(bias[ca + 2], bias[ca + 3]);
#pragma unroll
        for (int j = 0; j < RPTN; j++) { acc0[j] = b01; acc1[j] = b23; }
    } else {
        float b0 = bias[ca], b1v = bias[ca + 1], b2v = bias[ca + 2], b3v = bias[ca + 3];
#pragma unroll
        for (int j = 0; j < RPTN; j++) {
            int gr = row0 + r0 + j;
            float dv = (gr < nrows) ? deg[gr] : 0.f;
            acc0[j] = pack2(dv * b0, dv * b1v);
            acc1[j] = pack2(dv * b2v, dv * b3v);
        }
    }

#pragma unroll
    for (int kq = 0; kq < 16; kq++) {
        int k = 4 * kq;
        ulonglong2 w0 = *(const ulonglong2*)&wsT[k + 0][ca];
        ulonglong2 w1 = *(const ulonglong2*)&wsT[k + 1][ca];
        ulonglong2 w2 = *(const ulonglong2*)&wsT[k + 2][ca];
        ulonglong2 w3 = *(const ulonglong2*)&wsT[k + 3][ca];
#pragma unroll
        for (int j = 0; j < RPTN; j++) {
            float4 x4 = __ldg((const float4*)&X[grj[j] * EMB + k]);   // L1 broadcast
            u64 xx;
            xx = pack2(x4.x, x4.x); fma2(acc0[j], xx, w0.x); fma2(acc1[j], xx, w0.y);
            xx = pack2(x4.y, x4.y); fma2(acc0[j], xx, w1.x); fma2(acc1[j], xx, w1.y);
            xx = pack2(x4.z, x4.z); fma2(acc0[j], xx, w2.x); fma2(acc1[j], xx, w2.y);
            xx = pack2(x4.w, x4.w); fma2(acc0[j], xx, w3.x); fma2(acc1[j], xx, w3.y);
        }
    }

    float s0 = 0.f, s1 = 0.f, s2 = 0.f, s3 = 0.f;
    float q0 = 0.f, q1 = 0.f, q2 = 0.f, q3 = 0.f;
#pragma unroll
    for (int j = 0; j < RPTN; j++) {
        int gr = row0 + r0 + j;
        if (gr < nrows) {
            float2 v01 = unpack2(acc0[j]);
            float2 v23 = unpack2(acc1[j]);
            *(float4*)&out[gr * EMB + ca] = make_float4(v01.x, v01.y, v23.x, v23.y);
            if (MODE == 2) {
                s0 += v01.x; q0 += v01.x * v01.x;
                s1 += v01.y; q1 += v01.y * v01.y;
                s2 += v23.x; q2 += v23.x * v23.x;
                s3 += v23.y; q3 += v23.y * v23.y;
            }
        }
    }

    if (MODE == 2) {
        if (t < 128) red[t] = 0.f;
        __syncthreads();
        atomicAdd(&red[ca + 0], s0);
        atomicAdd(&red[ca + 1], s1);
        atomicAdd(&red[ca + 2], s2);
        atomicAdd(&red[ca + 3], s3);
        atomicAdd(&red[64 + ca + 0], q0);
        atomicAdd(&red[64 + ca + 1], q1);
        atomicAdd(&red[64 + ca + 2], q2);
        atomicAdd(&red[64 + ca + 3], q3);
        __syncthreads();
        if (t < 128) atomicAdd(&d_stats[128 + t], red[t]);
    }
}

// ---------------- merged projections: left (MODE 1) + right (MODE 0) --------
__global__ __launch_bounds__(256) void proj_kernel(
    const float* __restrict__ left, const float* __restrict__ Wl,
    const float* __restrict__ bl,
    const float* __restrict__ right, const float* __restrict__ Wr,
    int NL, int NR, int nbL)
{
    __shared__ float wsT[EMB][WPAD];
    if ((int)blockIdx.x < nbL) {
        gemm_body<1>(left, Wl, bl, nullptr, d_LP, NL, blockIdx.x, wsT, nullptr);
    } else {
        gemm_body<0>(right, Wr, nullptr, nullptr, d_RP, NR, blockIdx.x - nbL, wsT, nullptr);
    }
}

// ---------------- conv GEMM (MODE 2) ------------------------------------------
__global__ __launch_bounds__(256) void conv_kernel(
    const float* __restrict__ Wf, const float* __restrict__ bf, int NR)
{
    __shared__ float wsT[EMB][WPAD];
    __shared__ float red[128];
    gemm_body<2>(d_S, Wf, bf, d_deg, d_conv, NR, blockIdx.x, wsT, red);
}

// ---------------- edge pass 1: bn1 stats + degree ----------------------------
__global__ __launch_bounds__(192) void edge_stats_kernel(
    const int* __restrict__ ei, const float* __restrict__ ef,
    const float* __restrict__ Wedge, int NE)
{
    int t = threadIdx.x;
    int g = t & 15;
    int slot = blockIdx.x * 12 + (t >> 4);
    int step = gridDim.x * 12;
    float4 we = ((const float4*)Wedge)[g];
    float4 sum = make_float4(0.f, 0.f, 0.f, 0.f);
    float4 sq = make_float4(0.f, 0.f, 0.f, 0.f);

    for (int e = slot; e < NE; e += 2 * step) {
        int eB = e + step;
        bool hasB = eB < NE;
        int eBc = hasB ? eB : e;
        int i0a = ei[e];
        int i1a = ei[NE + e];
        float fa = ef[e];
        int i0b = ei[eBc];
        int i1b = ei[NE + eBc];
        float fb = ef[eBc];
        float4 lpA = ((const float4*)d_LP)[i0a * 16 + g];
        float4 rpA = ((const float4*)d_RP)[i1a * 16 + g];
        float4 lpB = ((const float4*)d_LP)[i0b * 16 + g];
        float4 rpB = ((const float4*)d_RP)[i1b * 16 + g];

        float4 jA;
        jA.x = fmaf(fa, we.x, lpA.x + rpA.x);
        jA.y = fmaf(fa, we.y, lpA.y + rpA.y);
        jA.z = fmaf(fa, we.z, lpA.z + rpA.z);
        jA.w = fmaf(fa, we.w, lpA.w + rpA.w);
        sum.x += jA.x; sum.y += jA.y; sum.z += jA.z; sum.w += jA.w;
        sq.x += jA.x * jA.x; sq.y += jA.y * jA.y;
        sq.z += jA.z * jA.z; sq.w += jA.w * jA.w;

        float m = hasB ? 1.f : 0.f;
        float4 jB;
        jB.x = fmaf(fb, we.x, lpB.x + rpB.x);
        jB.y = fmaf(fb, we.y, lpB.y + rpB.y);
        jB.z = fmaf(fb, we.z, lpB.z + rpB.z);
        jB.w = fmaf(fb, we.w, lpB.w + rpB.w);
        sum.x += m * jB.x; sum.y += m * jB.y;
        sum.z += m * jB.z; sum.w += m * jB.w;
        sq.x += m * jB.x * jB.x; sq.y += m * jB.y * jB.y;
        sq.z += m * jB.z * jB.z; sq.w += m * jB.w * jB.w;

        if (g == 0) {
            atomicAdd(&d_deg[i1a], 1.f);
            if (hasB) atomicAdd(&d_deg[i1b], 1.f);
        }
    }

    __shared__ float red[128];
    if (t < 128) red[t] = 0.f;
    __syncthreads();
    atomicAdd(&red[4 * g + 0], sum.x);
    atomicAdd(&red[4 * g + 1], sum.y);
    atomicAdd(&red[4 * g + 2], sum.z);
    atomicAdd(&red[4 * g + 3], sum.w);
    atomicAdd(&red[64 + 4 * g + 0], sq.x);
    atomicAdd(&red[64 + 4 * g + 1], sq.y);
    atomicAdd(&red[64 + 4 * g + 2], sq.z);
    atomicAdd(&red[64 + 4 * g + 3], sq.w);
    __syncthreads();
    if (t < 128) atomicAdd(&d_stats[t], red[t]);
}

// ---------------- edge pass 2: fused bn1 finalize + scatter ------------------
__global__ __launch_bounds__(192) void edge_scatter_kernel(
    const int* __restrict__ ei, const float* __restrict__ ef,
    const float* __restrict__ Wedge,
    const float* __restrict__ gamma, const float* __restrict__ beta,
    float cnt, int NE)
{
    __shared__ float4 s_sc[16], s_sh[16];
    int t = threadIdx.x;
    if (t < 16) {
        float4 sm = ((const float4*)d_stats)[t];        // sums
        float4 qm = ((const float4*)d_stats)[16 + t];   // sumsq
        float4 gm = ((const float4*)gamma)[t];
        float4 bm = ((const float4*)beta)[t];
        float4 sc, sh;
        float mean, var;
        mean = sm.x / cnt; var = qm.x / cnt - mean * mean;
        sc.x = gm.x * rsqrtf(var + BN_EPS); sh.x = bm.x - mean * sc.x;
        mean = sm.y / cnt; var = qm.y / cnt - mean * mean;
        sc.y = gm.y * rsqrtf(var + BN_EPS); sh.y = bm.y - mean * sc.y;
        mean = sm.z / cnt; var = qm.z / cnt - mean * mean;
        sc.z = gm.z * rsqrtf(var + BN_EPS); sh.z = bm.z - mean * sc.z;
        mean = sm.w / cnt; var = qm.w / cnt - mean * mean;
        sc.w = gm.w * rsqrtf(var + BN_EPS); sh.w = bm.w - mean * sc.w;
        s_sc[t] = sc; s_sh[t] = sh;
    }
    __syncthreads();

    int tid = blockIdx.x * 192 + t;
    int p = tid >> 4;
    int g = tid & 15;
    int eA = 2 * p;
    if (eA >= NE) return;
    int eB = eA + 1;
    bool hasB = eB < NE;
    int eBc = hasB ? eB : eA;

    float4 we = ((const float4*)Wedge)[g];
    float4 s = s_sc[g];
    float4 sh = s_sh[g];

    int i0a = ei[eA];
    int i1a = ei[NE + eA];
    float fa = ef[eA];
    int i0b = ei[eBc];
    int i1b = ei[NE + eBc];
    float fb = ef[eBc];
    float4 lpA = ((const float4*)d_LP)[i0a * 16 + g];
    float4 rpA = ((const float4*)d_RP)[i1a * 16 + g];
    float4 lpB = ((const float4*)d_LP)[i0b * 16 + g];
    float4 rpB = ((const float4*)d_RP)[i1b * 16 + g];

    float4 vA;
    vA.x = fmaxf(fmaf(fmaf(fa, we.x, lpA.x + rpA.x), s.x, sh.x), 0.f);
    vA.y = fmaxf(fmaf(fmaf(fa, we.y, lpA.y + rpA.y), s.y, sh.y), 0.f);
    vA.z = fmaxf(fmaf(fmaf(fa, we.z, lpA.z + rpA.z), s.z, sh.z), 0.f);
    vA.w = fmaxf(fmaf(fmaf(fa, we.w, lpA.w + rpA.w), s.w, sh.w), 0.f);
    float* pa = &d_S[i1a * EMB + 4 * g];
    asm volatile("red.global.add.v4.f32 [%0], {%1,%2,%3,%4};"
                 :: "l"(pa), "f"(vA.x), "f"(vA.y), "f"(vA.z), "f"(vA.w) : "memory");

    if (hasB) {
        float4 vB;
        vB.x = fmaxf(fmaf(fmaf(fb, we.x, lpB.x + rpB.x), s.x, sh.x), 0.f);
        vB.y = fmaxf(fmaf(fmaf(fb, we.y, lpB.y + rpB.y), s.y, sh.y), 0.f);
        vB.z = fmaxf(fmaf(fmaf(fb, we.z, lpB.z + rpB.z), s.z, sh.z), 0.f);
        vB.w = fmaxf(fmaf(fmaf(fb, we.w, lpB.w + rpB.w), s.w, sh.w), 0.f);
        float* pb = &d_S[i1b * EMB + 4 * g];
        asm volatile("red.global.add.v4.f32 [%0], {%1,%2,%3,%4};"
                     :: "l"(pb), "f"(vB.x), "f"(vB.y), "f"(vB.z), "f"(vB.w) : "memory");
    }
}

// ---------------- fused output layers + bn2 finalize -------------------------
__global__ __launch_bounds__(256) void out_fused_kernel(
    const float* __restrict__ right,
    const float* __restrict__ g2, const float* __restrict__ bt2, float cnt2,
    const float* __restrict__ W1, const float* __restrict__ b1,
    const float* __restrict__ W2, const float* __restrict__ b2,
    float* __restrict__ out, int nrows)
{
    __shared__ float xs[TROWS][EMB];
    __shared__ float wsT[EMB][WPAD];
    __shared__ float sc2[EMB], sh2[EMB];

    int t = threadIdx.x;
    int cg = t & 15;
    int rg = t >> 4;
    int row0 = blockIdx.x * TROWS;
    int ca = 4 * cg;
    int r0 = rg * RPTN;

    if (t < 64) {
        float mean = d_stats[128 + t] / cnt2;
        float var = d_stats[192 + t] / cnt2 - mean * mean;
        float sc = g2[t] * rsqrtf(var + BN_EPS);
        sc2[t] = sc;
        sh2[t] = bt2[t] - mean * sc;
    }

    u64 acc0[RPTN], acc1[RPTN];
    {
        u64 b01 = pack2(b1[ca], b1[ca + 1]);
        u64 b23 = pack2(b1[ca + 2], b1[ca + 3]);
#pragma unroll
        for (int j = 0; j < RPTN; j++) { acc0[j] = b01; acc1[j] = b23; }
    }

#pragma unroll
    for (int phase = 0; phase < 2; phase++) {
        int koff = phase * 64;
#pragma unroll
        for (int p = 0; p < 4; p++) {
            int i = t + p * 256;
            int c = i >> 4;
            int k4 = (i & 15) * 4;
            float4 w4 = *(const float4*)&W1[c * 128 + koff + k4];
            wsT[k4 + 0][c] = w4.x;
            wsT[k4 + 1][c] = w4.y;
            wsT[k4 + 2][c] = w4.z;
            wsT[k4 + 3][c] = w4.w;
        }
        if (phase == 0) __syncthreads();   // sc2/sh2 ready before use below
#pragma unroll
        for (int p = 0; p < TROWS / 16; p++) {
            int i = t + p * 256;
            int r = i >> 4;
            int c4 = (i & 15) * 4;
            int gr = row0 + r;
            float4 v;
            if (gr < nrows) {
                if (phase == 0) {
                    v = *(const float4*)&d_conv[gr * EMB + c4];
                    v.x = v.x * sc2[c4 + 0] + sh2[c4 + 0];
                    v.y = v.y * sc2[c4 + 1] + sh2[c4 + 1];
                    v.z = v.z * sc2[c4 + 2] + sh2[c4 + 2];
                    v.w = v.w * sc2[c4 + 3] + sh2[c4 + 3];
                } else {
                    v = *(const float4*)&right[gr * EMB + c4];
                }
            } else {
                v = make_float4(0.f, 0.f, 0.f, 0.f);
            }
            *(float4*)&xs[r][c4] = v;
        }
        __syncthreads();

#pragma unroll
        for (int kq = 0; kq < 16; kq++) {
            int k = 4 * kq;
            ulonglong2 w0 = *(const ulonglong2*)&wsT[k + 0][ca];
            ulonglong2 w1 = *(const ulonglong2*)&wsT[k + 1][ca];
            ulonglong2 w2 = *(const ulonglong2*)&wsT[k + 2][ca];
            ulonglong2 w3 = *(const ulonglong2*)&wsT[k + 3][ca];
#pragma unroll
            for (int j = 0; j < RPTN; j++) {
                float4 x4 = *(const float4*)&xs[r0 + j][k];
                u64 xx;
                xx = pack2(x4.x, x4.x); fma2(acc0[j], xx, w0.x); fma2(acc1[j], xx, w0.y);
                xx = pack2(x4.y, x4.y); fma2(acc0[j], xx, w1.x); fma2(acc1[j], xx, w1.y);
                xx = pack2(x4.z, x4.z); fma2(acc0[j], xx, w2.x); fma2(acc1[j], xx, w2.y);
                xx = pack2(x4.w, x4.w); fma2(acc0[j], xx, w3.x); fma2(acc1[j], xx, w3.y);
            }
        }
        __syncthreads();
    }

    // h = relu(acc) -> xs ; stage W2 ; second GEMM in-block
#pragma unroll
    for (int j = 0; j < RPTN; j++) {
        float2 v01 = unpack2(acc0[j]);
        float2 v23 = unpack2(acc1[j]);
        *(float4*)&xs[r0 + j][ca] = make_float4(fmaxf(v01.x, 0.f), fmaxf(v01.y, 0.f),
                                                fmaxf(v23.x, 0.f), fmaxf(v23.y, 0.f));
    }
#pragma unroll
    for (int p = 0; p < 4; p++) {
        int i = t + p * 256;
        int c = i >> 4;
        int k4 = (i & 15) * 4;
        float4 w4 = *(const float4*)&W2[c * EMB + k4];
        wsT[k4 + 0][c] = w4.x;
        wsT[k4 + 1][c] = w4.y;
        wsT[k4 + 2][c] = w4.z;
        wsT[k4 + 3][c] = w4.w;
    }
    __syncthreads();

    u64 o0[RPTN], o1[RPTN];
    {
        u64 b01 = pack2(b2[ca], b2[ca + 1]);
        u64 b23 = pack2(b2[ca + 2], b2[ca + 3]);
#pragma unroll
        for (int j = 0; j < RPTN; j++) { o0[j] = b01; o1[j] = b23; }
    }

#pragma unroll
    for (int kq = 0; kq < 16; kq++) {
        int k = 4 * kq;
        ulonglong2 w0 = *(const ulonglong2*)&wsT[k + 0][ca];
        ulonglong2 w1 = *(const ulonglong2*)&wsT[k + 1][ca];
        ulonglong2 w2 = *(const ulonglong2*)&wsT[k + 2][ca];
        ulonglong2 w3 = *(const ulonglong2*)&wsT[k + 3][ca];
#pragma unroll
        for (int j = 0; j < RPTN; j++) {
            float4 x4 = *(const float4*)&xs[r0 + j][k];
            u64 xx;
            xx = pack2(x4.x, x4.x); fma2(o0[j], xx, w0.x); fma2(o1[j], xx, w0.y);
            xx = pack2(x4.y, x4.y); fma2(o0[j], xx, w1.x); fma2(o1[j], xx, w1.y);
            xx = pack2(x4.z, x4.z); fma2(o0[j], xx, w2.x); fma2(o1[j], xx, w2.y);
            xx = pack2(x4.w, x4.w); fma2(o0[j], xx, w3.x); fma2(o1[j], xx, w3.y);
        }
    }

#pragma unroll
    for (int j = 0; j < RPTN; j++) {
        int gr = row0 + r0 + j;
        if (gr < nrows) {
            float2 v01 = unpack2(o0[j]);
            float2 v23 = unpack2(o1[j]);
            *(float4*)&out[gr * EMB + ca] = make_float4(fmaxf(v01.x, 0.f), fmaxf(v01.y, 0.f),
                                                        fmaxf(v23.x, 0.f), fmaxf(v23.y, 0.f));
        }
    }
}

// ---------------- launch -----------------------------------------------------
extern "C" void kernel_launch(void* const* d_in, const int* in_sizes, int n_in,
                              void* d_out, int out_size)
{
    (void)n_in; (void)out_size;
    const float* left   = (const float*)d_in[0];
    const int*   ei     = (const int*)d_in[1];
    const float* ef     = (const float*)d_in[2];
    const float* right  = (const float*)d_in[3];
    const float* W_left  = (const float*)d_in[5];
    const float* b_left  = (const float*)d_in[6];
    const float* W_edge  = (const float*)d_in[7];
    const float* W_right = (const float*)d_in[8];
    const float* g1      = (const float*)d_in[9];
    const float* bt1     = (const float*)d_in[10];
    const float* W_final = (const float*)d_in[11];
    const float* b_final = (const float*)d_in[12];
    const float* g2      = (const float*)d_in[13];
    const float* bt2     = (const float*)d_in[14];
    const float* W1      = (const float*)d_in[15];
    const float* b1      = (const float*)d_in[16];
    const float* W2      = (const float*)d_in[17];
    const float* b2      = (const float*)d_in[18];
    float* out = (float*)d_out;

    int NL = in_sizes[0] / EMB;
    int NE = in_sizes[2];
    int NR = in_sizes[3] / EMB;

    float *pS, *pDeg, *pStats;
    cudaGetSymbolAddress((void**)&pS, d_S);
    cudaGetSymbolAddress((void**)&pDeg, d_deg);
    cudaGetSymbolAddress((void**)&pStats, d_stats);

    // zero atomically-accumulated scratch via memset nodes
    cudaMemsetAsync(pS, 0, (size_t)NR * EMB * sizeof(float), 0);
    cudaMemsetAsync(pDeg, 0, (size_t)NR * sizeof(float), 0);
    cudaMemsetAsync(pStats, 0, 256 * sizeof(float), 0);

    int nbL = (NL + TROWS - 1) / TROWS;
    int nbR = (NR + TROWS - 1) / TROWS;

    // 1. merged projections
    proj_kernel<<<nbL + nbR, 256>>>(left, W_left, b_left, right, W_right, NL, NR, nbL);
    // 2. edge pass 1: bn1 stats + degree
    edge_stats_kernel<<<1184, 192>>>(ei, ef, W_edge, NE);
    // 3. edge pass 2: fused bn1 finalize + scatter
    {
        int npairs = (NE + 1) / 2;
        int nthr = npairs * 16;
        edge_scatter_kernel<<<(nthr + 191) / 192, 192>>>(ei, ef, W_edge, g1, bt1, (float)NE, NE);
    }
    // 4. conv = S @ Wf.T + deg*bf ; bn2 stats
    conv_kernel<<<nbR, 256>>>(W_final, b_final, NR);
    // 5. fused bn2 finalize + out1 + out2
    out_fused_kernel<<<nbR, 256>>>(right, g2, bt2, (float)NR, W1, b1, W2, b2, out, NR);
}